// round 2
// baseline (speedup 1.0000x reference)
#include <cuda_runtime.h>

// FoldLayer (col2im overlap-add), gather formulation.
// patches: (B=16, GH=64, GW=64, K*K*C = 9*128) fp32, kernel-major [i*3+j][c]
// out:     (B=16, 128, 128, C=128) fp32  (padded canvas cropped by PAD=1)
//
// For output (oy, ox): y_pad = oy+1, x_pad = ox+1.
//   tap parity: i ≡ y_pad (mod 2), j ≡ x_pad (mod 2)
//   odd  y_pad -> { (i=1, y=(y_pad-1)/2) }                      (always valid)
//   even y_pad -> { (i=2, y=(y_pad-2)/2) } ∪ { (i=0, y=y_pad/2) if y_pad != 128 }
//
// Vectorized float4 over channels: 32 float4 lanes per pixel, one warp per pixel.

#define C4 32            // 128 channels / 4
#define PSTRIDE 288      // 1152 floats / 4 = float4 stride per patch pixel

__global__ void __launch_bounds__(256) fold_gather_kernel(
    const float4* __restrict__ p, float4* __restrict__ out)
{
    int idx = blockIdx.x * blockDim.x + threadIdx.x;  // over 8,388,608 float4
    int c4  = idx & (C4 - 1);
    int pix = idx >> 5;
    int ox  = pix & 127;
    int r   = pix >> 7;
    int oy  = r & 127;
    int b   = r >> 7;

    int y_pad = oy + 1;
    int x_pad = ox + 1;

    // y taps
    int ys0, is0, ys1 = 0, is1 = 0, ny;
    if (y_pad & 1) {
        ys0 = (y_pad - 1) >> 1; is0 = 1; ny = 1;
    } else {
        ys0 = (y_pad - 2) >> 1; is0 = 2;
        if (y_pad != 128) { ys1 = y_pad >> 1; is1 = 0; ny = 2; }
        else ny = 1;
    }
    // x taps
    int xs0, js0, xs1 = 0, js1 = 0, nx;
    if (x_pad & 1) {
        xs0 = (x_pad - 1) >> 1; js0 = 1; nx = 1;
    } else {
        xs0 = (x_pad - 2) >> 1; js0 = 2;
        if (x_pad != 128) { xs1 = x_pad >> 1; js1 = 0; nx = 2; }
        else nx = 1;
    }

    float4 acc = make_float4(0.f, 0.f, 0.f, 0.f);

    int brow = b * 64;  // b*GH
    #pragma unroll
    for (int a = 0; a < 2; a++) {
        if (a >= ny) break;
        int y = (a == 0) ? ys0 : ys1;
        int i = (a == 0) ? is0 : is1;
        int rowbase = (brow + y) * 64;
        #pragma unroll
        for (int bb = 0; bb < 2; bb++) {
            if (bb >= nx) break;
            int x = (bb == 0) ? xs0 : xs1;
            int j = (bb == 0) ? js0 : js1;
            int base = (rowbase + x) * PSTRIDE + (i * 3 + j) * C4 + c4;
            float4 v = __ldg(&p[base]);
            acc.x += v.x; acc.y += v.y; acc.z += v.z; acc.w += v.w;
        }
    }

    out[idx] = acc;
}

extern "C" void kernel_launch(void* const* d_in, const int* in_sizes, int n_in,
                              void* d_out, int out_size) {
    const float4* p = (const float4*)d_in[0];
    float4* out = (float4*)d_out;
    int n4 = out_size / 4;                 // 8,388,608
    int threads = 256;
    int blocks = (n4 + threads - 1) / threads;  // 32,768
    fold_gather_kernel<<<blocks, threads>>>(p, out);
}